// round 17
// baseline (speedup 1.0000x reference)
#include <cuda_runtime.h>
#include <cuda_fp16.h>
#include <math.h>

#define BB 2
#define KK 256
#define RR 32
#define DD 192
#define NH 6
#define DH 32
#define NTOK 1024   // 32*32 L4 tokens per batch

// ---------------- scratch (device globals; no allocs allowed) ----------------
__device__ __half    d_ft0[(size_t)BB*NH*128*128*32];  // level0 channels-last fp16
__device__ __half    d_ft1[(size_t)BB*NH*64*64*32];    // level1
__device__ __half    d_ft2[(size_t)BB*NH*32*32*32];    // level2
__device__ float     d_gpre[(size_t)BB*NTOK*DD];       // g @ W_u[:,192:384]
__device__ float     d_hpre[(size_t)BB*KK*DD];         // h @ W_u[:,0:192] + b_u
__device__ float     d_wuT [(size_t)416*192];          // W_u^T  [c][d]
__device__ unsigned  d_wdK [(size_t)192*216];          // delta+a tf32 bits, [k][o]
__device__ unsigned  d_woH [(size_t)192*192];          // W_o tf32 hi bits, [k][o]
__device__ unsigned  d_woL [(size_t)192*192];          // W_o tf32 lo bits, [k][o]

// ---------------- tf32 helpers ------------------------------------------------
__device__ __forceinline__ unsigned tf32_rna(float x) {
    unsigned u;
    asm("cvt.rna.tf32.f32 %0, %1;" : "=r"(u) : "f"(x));
    return u;
}
__device__ __forceinline__ void mma_tf32(float& c0, float& c1, float& c2, float& c3,
                                         unsigned a0, unsigned a1, unsigned a2, unsigned a3,
                                         unsigned b0, unsigned b1) {
    asm("mma.sync.aligned.m16n8k8.row.col.f32.tf32.tf32.f32 "
        "{%0,%1,%2,%3}, {%4,%5,%6,%7}, {%8,%9}, {%0,%1,%2,%3};"
        : "+f"(c0), "+f"(c1), "+f"(c2), "+f"(c3)
        : "r"(a0), "r"(a1), "r"(a2), "r"(a3), "r"(b0), "r"(b1));
}
// fast tanh via MUFU EX2 (abs err ~1e-6; exact saturation at +-inf)
__device__ __forceinline__ float ftanh(float x) {
    float e = __expf(2.f * x);
    return 1.f - __fdividef(2.f, e + 1.f);
}

// ---------------- vectorized per-row transpose helper -------------------------
template<int WL>
__device__ __forceinline__ void transpose_row(const float* __restrict__ base,
                                              __half* __restrict__ orow,
                                              float (*s)[129], int tid)
{
    const int NV = 32 * WL / 4;
    #pragma unroll
    for (int i = tid; i < NV; i += 256) {
        int c  = i / (WL/4);
        int xv = i - c * (WL/4);
        float4 v = *(const float4*)(base + (size_t)c * WL * WL + xv*4);
        s[c][xv*4 + 0] = v.x;
        s[c][xv*4 + 1] = v.y;
        s[c][xv*4 + 2] = v.z;
        s[c][xv*4 + 3] = v.w;
    }
    __syncthreads();
    const int NW = WL * 4;
    #pragma unroll
    for (int i = tid; i < NW; i += 256) {
        int x  = i >> 2;
        int c8 = (i & 3) * 8;
        __half hv[8];
        #pragma unroll
        for (int j = 0; j < 8; ++j)
            hv[j] = __float2half(s[c8 + j][x]);
        *(uint4*)(orow + (size_t)x*32 + c8) = *(const uint4*)hv;
    }
    __syncthreads();
}

// ---------------- merged prep: weight layouts + row-vectorized transpose -----
// blocks 0..63: weight prep; 64..1599: L0 rows; 1600..2367: L1; 2368..2751: L2
__global__ void prep_all_kernel(const float* __restrict__ wu,
                                const float* __restrict__ wd,
                                const float* __restrict__ wa,
                                const float* __restrict__ wo,
                                const float* __restrict__ L2p,
                                const float* __restrict__ L3p,
                                const float* __restrict__ L4p)
{
    __shared__ float s[32][129];
    int tid = threadIdx.x;
    if (blockIdx.x < 64) {
        int i0 = blockIdx.x * blockDim.x + tid;
        int stride = 64 * blockDim.x;
        for (int i = i0; i < 416*192; i += stride) {
            int c = i / 192, d = i - c*192;
            d_wuT[i] = wu[(size_t)d*416 + c];
        }
        for (int i = i0; i < 192*216; i += stride) {
            int c = i / 216, o = i - c*216;
            float w = (o < 144) ? wd[(size_t)o*192 + c] : wa[(size_t)(o-144)*192 + c];
            d_wdK[i] = tf32_rna(w);
        }
        for (int i = i0; i < 192*192; i += stride) {
            int c = i / 192, o = i - c*192;
            float w = wo[(size_t)o*192 + c];
            unsigned hb = tf32_rna(w);
            d_woH[i] = hb;
            d_woL[i] = tf32_rna(w - __uint_as_float(hb));
        }
        return;
    }
    int bid = blockIdx.x - 64;
    if (bid < 1536) {
        int bh = bid >> 7, y = bid & 127;
        int b = bh / NH, hh = bh % NH;
        const float* base = L2p + (((size_t)b*DD + hh*DH) * 128 + y) * 128;
        __half* orow = d_ft0 + (((size_t)bh * 128 + y) * 128) * 32;
        transpose_row<128>(base, orow, s, tid);
    } else if (bid < 2304) {
        int t = bid - 1536;
        int bh = t >> 6, y = t & 63;
        int b = bh / NH, hh = bh % NH;
        const float* base = L3p + (((size_t)b*DD + hh*DH) * 64 + y) * 64;
        __half* orow = d_ft1 + (((size_t)bh * 64 + y) * 64) * 32;
        transpose_row<64>(base, orow, s, tid);
    } else {
        int t = bid - 2304;
        int bh = t >> 5, y = t & 31;
        int b = bh / NH, hh = bh % NH;
        const float* base = L4p + (((size_t)b*DD + hh*DH) * 32 + y) * 32;
        __half* orow = d_ft2 + (((size_t)bh * 32 + y) * 32) * 32;
        transpose_row<32>(base, orow, s, tid);
    }
}

// ---------------- precompute: X @ WuT slice; 8 rows/block, 320 blocks --------
__global__ void __launch_bounds__(192)
pre_fast_kernel(const float* __restrict__ g, const float* __restrict__ h,
                const float* __restrict__ bias)
{
    __shared__ float xs[8*192];
    int bx = blockIdx.x;
    const float* X; float* outp; int colOff, r0;
    bool useBias;
    if (bx < 256) { X = g; outp = d_gpre; colOff = 192; r0 = bx*8; useBias = false; }
    else          { X = h; outp = d_hpre; colOff = 0;   r0 = (bx-256)*8; useBias = true; }
    int tid = threadIdx.x;
    for (int i = tid; i < 8*192; i += 192)
        xs[i] = X[(size_t)r0*192 + i];
    __syncthreads();
    float acc[8];
    #pragma unroll
    for (int q = 0; q < 8; ++q) acc[q] = 0.f;
    const float* wbase = d_wuT + (size_t)colOff*192 + tid;
    #pragma unroll 4
    for (int c4 = 0; c4 < 48; ++c4) {
        float w0 = wbase[(4*c4    )*192];
        float w1 = wbase[(4*c4 + 1)*192];
        float w2 = wbase[(4*c4 + 2)*192];
        float w3 = wbase[(4*c4 + 3)*192];
        #pragma unroll
        for (int q = 0; q < 8; ++q) {
            float4 xv = *(const float4*)(&xs[q*192 + 4*c4]);
            acc[q] += xv.x*w0 + xv.y*w1 + xv.z*w2 + xv.w*w3;
        }
    }
    float bb = useBias ? bias[tid] : 0.f;
    #pragma unroll
    for (int q = 0; q < 8; ++q)
        outp[(size_t)(r0 + q)*192 + tid] = acc[q] + bb;
}

// ---------------- main fused kernel (tensor-core B/D via mma.sync tf32) ------
#define SM_UT   0          // u_t [c*34 + r], 192*34 = 6528  (ht in C; hi in D)
#define SM_OFFS 6528       // offs [32*144] = 4608 (phi aliases; lo_t in D)
#define SM_PHI  6528
#define SM_WTS  11136      // wts [32*72] = 2304 (LN partials alias)
#define SM_AX   13440
#define SM_AY   13472
#define SM_IDX  13504
#define SM_MU   13536
#define SM_RS   13568
#define SM_TOTF 13600

__global__ void __launch_bounds__(256, 4)
main_kernel(const int*   __restrict__ top_indices,
            const float* __restrict__ qc,
            const float* __restrict__ ln_g,
            const float* __restrict__ ln_b,
            const float* __restrict__ w_delta_b,
            const float* __restrict__ w_a_b,
            const float* __restrict__ w_o_b,
            const float* __restrict__ e_def,
            float* __restrict__ out)
{
    extern __shared__ float sm[];
    float* u_t  = sm + SM_UT;     // [c*34 + r]
    float* offs = sm + SM_OFFS;
    float* phi  = sm + SM_PHI;
    float* wts  = sm + SM_WTS;
    float* ax_s = sm + SM_AX;
    float* ay_s = sm + SM_AY;
    int*   idx_s = (int*)(sm + SM_IDX);
    float* mu_s = sm + SM_MU;
    float* rs_s = sm + SM_RS;

    int tid  = threadIdx.x;
    int lane = tid & 31;
    int wid  = tid >> 5;
    int bk   = blockIdx.x;         // b*256 + k
    int b    = bk >> 8;

    // ---- anchors ----
    if (tid < 32) {
        int id = top_indices[(size_t)bk * RR + tid];
        idx_s[tid] = id;
        ax_s[tid] = (float)(id & 31) * 32.f + 16.f;
        ay_s[tid] = (float)(id >> 5) * 32.f + 16.f;
    }
    __syncthreads();

    // ---- fourier PE (fast sincos) ----
    {
        int r = tid >> 3, j = tid & 7;
        float qx = qc[(size_t)bk*2 + 0];
        float qy = qc[(size_t)bk*2 + 1];
        float dxn  = (ax_s[r] - qx) * (1.f/1024.f);
        float dyn_ = (ay_s[r] - qy) * (1.f/1024.f);
        float f = (float)(1 << j);
        float xa = (dxn  * f) * 6.283185307179586f;
        float ya = (dyn_ * f) * 6.283185307179586f;
        float sx, cx, sy, cy;
        __sincosf(xa, &sx, &cx);
        __sincosf(ya, &sy, &cy);
        phi[r*32 + j]      = sx;
        phi[r*32 + 8 + j]  = cx;
        phi[r*32 + 16 + j] = sy;
        phi[r*32 + 24 + j] = cy;
    }
    __syncthreads();

    // ---- phase A: gelu(hpre + gpre[idx] + phi @ Wphi^T), two 16-wide K-chunks
    if (tid < 192) {
        {
            float w16[16];
            #pragma unroll
            for (int i = 0; i < 16; ++i)
                w16[i] = d_wuT[(size_t)(384 + i)*192 + tid];
            #pragma unroll 2
            for (int r = 0; r < 32; ++r) {
                const float4* ph = (const float4*)(phi + r*32);
                float acc = 0.f;
                #pragma unroll
                for (int c4 = 0; c4 < 4; ++c4) {
                    float4 pv = ph[c4];
                    acc += pv.x*w16[4*c4] + pv.y*w16[4*c4+1]
                         + pv.z*w16[4*c4+2] + pv.w*w16[4*c4+3];
                }
                u_t[tid*34 + r] = acc;
            }
        }
        {
            float w16[16];
            #pragma unroll
            for (int i = 0; i < 16; ++i)
                w16[i] = d_wuT[(size_t)(400 + i)*192 + tid];
            float hbase = d_hpre[(size_t)bk*192 + tid];
            for (int rb = 0; rb < 32; rb += 4) {
                float gv[4];
                #pragma unroll
                for (int q = 0; q < 4; ++q)
                    gv[q] = d_gpre[((size_t)(b*NTOK + idx_s[rb + q])) * 192 + tid];
                #pragma unroll
                for (int q = 0; q < 4; ++q) {
                    int r = rb + q;
                    float acc = u_t[tid*34 + r] + hbase + gv[q];
                    const float4* ph = (const float4*)(phi + r*32 + 16);
                    #pragma unroll
                    for (int c4 = 0; c4 < 4; ++c4) {
                        float4 pv = ph[c4];
                        acc += pv.x*w16[4*c4] + pv.y*w16[4*c4+1]
                             + pv.z*w16[4*c4+2] + pv.w*w16[4*c4+3];
                    }
                    float gel = 0.5f * acc * (1.f + erff(acc * 0.70710678118654752f));
                    u_t[tid*34 + r] = gel;
                }
            }
        }
    }
    __syncthreads();

    // ---- LN stats ----
    {
        float s1 = 0.f, s2 = 0.f;
        int c0 = wid * 24;
        for (int cc = c0; cc < c0 + 24; ++cc) {
            float v = u_t[cc*34 + lane];
            s1 += v; s2 += v*v;
        }
        wts[wid*32 + lane]       = s1;
        wts[256 + wid*32 + lane] = s2;
    }
    __syncthreads();
    if (tid < 32) {
        float s1 = 0.f, s2 = 0.f;
        #pragma unroll
        for (int w = 0; w < 8; ++w) {
            s1 += wts[w*32 + tid];
            s2 += wts[256 + w*32 + tid];
        }
        float mu  = s1 * (1.f/192.f);
        float var = s2 * (1.f/192.f) - mu*mu;
        mu_s[tid] = mu;
        rs_s[tid] = rsqrtf(var + 1e-5f);
    }
    __syncthreads();

    // ---- LN apply + tf32 rounding (u consumed only by tf32 mma in B) -------
    if (tid < 192) {
        float gg = ln_g[tid], bb = ln_b[tid];
        #pragma unroll 4
        for (int r = 0; r < 32; ++r) {
            float v = u_t[tid*34 + r];
            float n = (v - mu_s[r]) * rs_s[r] * gg + bb;
            u_t[tid*34 + r] = __uint_as_float(tf32_rna(n));
        }
    }
    __syncthreads();

    // ---- phase B: [32x192] @ [192x216] via mma.sync tf32 (1-pass) ----------
    {
        int m0 = (wid & 1) * 16;
        int ng = wid >> 1;            // 0..3
        float acc[7][4];
        #pragma unroll
        for (int j = 0; j < 7; ++j)
            #pragma unroll
            for (int p = 0; p < 4; ++p) acc[j][p] = 0.f;
        const unsigned* up = (const unsigned*)u_t;
        int kl = lane & 3;
        int ml = lane >> 2;
        for (int ks = 0; ks < 24; ++ks) {
            int ka = ks*8 + kl;
            unsigned a0 = up[ka*34 + m0 + ml];
            unsigned a1 = up[ka*34 + m0 + ml + 8];
            unsigned a2 = up[(ka+4)*34 + m0 + ml];
            unsigned a3 = up[(ka+4)*34 + m0 + ml + 8];
            #pragma unroll
            for (int j = 0; j < 7; ++j) {
                int t = ng + 4*j;
                if (t < 27) {
                    int n = t*8 + ml;
                    unsigned b0 = d_wdK[(size_t)ka*216 + n];
                    unsigned b1 = d_wdK[(size_t)(ka+4)*216 + n];
                    mma_tf32(acc[j][0], acc[j][1], acc[j][2], acc[j][3],
                             a0, a1, a2, a3, b0, b1);
                }
            }
        }
        // epilogue: scatter fragments to offs / wts
        #pragma unroll
        for (int j = 0; j < 7; ++j) {
            int t = ng + 4*j;
            if (t < 27) {
                int obase = t*8 + (lane & 3)*2;
                int rbase = m0 + (lane >> 2);
                #pragma unroll
                for (int p = 0; p < 4; ++p) {
                    int o = obase + (p & 1);
                    int r = rbase + (p >> 1)*8;
                    float v = acc[j][p];
                    if (o < 144) {
                        int l = (o >> 3) % 3;
                        float sg = (l == 0) ? 4.f : ((l == 1) ? 2.f : 1.f);
                        offs[r*144 + o] = ftanh(v + w_delta_b[o]) * sg;
                    } else {
                        wts[r*72 + (o - 144)] = v + w_a_b[o - 144];
                    }
                }
            }
        }
    }
    __syncthreads();

    // ---- softmax over L*M=12 per (row, head) --------------------------------
    if (tid < 192) {
        int r = tid & 31, hh = tid >> 5;
        float* wp = wts + r*72 + hh*12;
        float mx = wp[0];
        #pragma unroll
        for (int t = 1; t < 12; ++t) mx = fmaxf(mx, wp[t]);
        float s = 0.f;
        #pragma unroll
        for (int t = 0; t < 12; ++t) { float e = __expf(wp[t] - mx); wp[t] = e; s += e; }
        float inv = 1.f / s;
        #pragma unroll
        for (int t = 0; t < 12; ++t) wp[t] *= inv;
    }
    __syncthreads();

    // ---- phase C: bilinear, branchless --------------------------------------
    {
        float* ht = u_t;                  // alias; u values dead now
        int qlane = lane >> 2;
        int c8i   = lane & 3;
        #pragma unroll
        for (int pass = 0; pass < 3; ++pass) {
            int uu = pass*64 + wid*8 + qlane;
            int r = uu & 31, hh = uu >> 5;
            float axr = ax_s[r], ayr = ay_s[r];
            const float* op = offs + r*144 + hh*24;
            const float* wp = wts + r*72 + hh*12;
            float acc[8];
            #pragma unroll
            for (int k = 0; k < 8; ++k) acc[k] = 0.f;
            #pragma unroll
            for (int l = 0; l < 3; ++l) {
                int Hl = 128 >> l, Wl = 128 >> l;
                const uint4* ft4;
                float scl;
                if (l == 0) { ft4 = (const uint4*)d_ft0 + ((size_t)(b*NH+hh)*128*128)*4 + c8i; scl = 0.125f; }
                else if (l == 1) { ft4 = (const uint4*)d_ft1 + ((size_t)(b*NH+hh)*64*64)*4 + c8i; scl = 0.0625f; }
                else { ft4 = (const uint4*)d_ft2 + ((size_t)(b*NH+hh)*32*32)*4 + c8i; scl = 0.03125f; }
                float afx = axr*scl, afy = ayr*scl;
                #pragma unroll
                for (int m = 0; m < 4; ++m) {
                    float px = afx + op[l*8 + 2*m];
                    float py = afy + op[l*8 + 2*m + 1];
                    float wgt = wp[l*4 + m];
                    float x0f = floorf(px), y0f = floorf(py);
                    float fx = px - x0f, fy = py - y0f;
                    int x0 = (int)x0f, y0 = (int)y0f;
                    float wx0 = 1.f - fx, wy0 = 1.f - fy;
                    float cw[4] = { wgt*wx0*wy0, wgt*fx*wy0, wgt*wx0*fy, wgt*fx*fy };
                    #pragma unroll
                    for (int corner = 0; corner < 4; ++corner) {
                        int xx = x0 + (corner & 1);
                        int yy = y0 + (corner >> 1);
                        bool valid = ((unsigned)xx < (unsigned)Wl) && ((unsigned)yy < (unsigned)Hl);
                        int xc = min(max(xx, 0), Wl - 1);
                        int yc = min(max(yy, 0), Hl - 1);
                        float w = valid ? cw[corner] : 0.f;
                        uint4 raw = ft4[((size_t)yc*Wl + xc)*4];
                        const __half2* hp = (const __half2*)&raw;
                        #pragma unroll
                        for (int k = 0; k < 4; ++k) {
                            float2 f2 = __half22float2(hp[k]);
                            acc[2*k]   += w * f2.x;
                            acc[2*k+1] += w * f2.y;
                        }
                    }
                }
            }
            int cbase = hh*32 + c8i*8;
            #pragma unroll
            for (int k = 0; k < 8; ++k)
                ht[(cbase + k)*34 + r] = acc[k];
        }
    }
    __syncthreads();

    // ---- hi/lo split of h for 3-pass tf32 mma (offs/wts dead now) -----------
    {
        float* lo_t = offs;           // 6528 floats fit in offs+wts region
        if (tid < 192) {
            #pragma unroll 4
            for (int r = 0; r < 32; ++r) {
                float hv = u_t[tid*34 + r];
                unsigned hb = tf32_rna(hv);
                float hf = __uint_as_float(hb);
                u_t[tid*34 + r] = hf;
                lo_t[tid*34 + r] = __uint_as_float(tf32_rna(hv - hf));
            }
        }
    }
    __syncthreads();

    // ---- phase D: [32x192] @ [192x192] via mma.sync tf32 (3-pass) ----------
    {
        const unsigned* hp = (const unsigned*)u_t;
        const unsigned* lp = (const unsigned*)offs;
        int m0 = (wid & 1) * 16;
        int ng = wid >> 1;            // 0..3
        float acc[6][4];
        #pragma unroll
        for (int j = 0; j < 6; ++j)
            #pragma unroll
            for (int p = 0; p < 4; ++p) acc[j][p] = 0.f;
        int kl = lane & 3;
        int ml = lane >> 2;
        for (int ks = 0; ks < 24; ++ks) {
            int ka = ks*8 + kl;
            unsigned ah0 = hp[ka*34 + m0 + ml];
            unsigned ah1 = hp[ka*34 + m0 + ml + 8];
            unsigned ah2 = hp[(ka+4)*34 + m0 + ml];
            unsigned ah3 = hp[(ka+4)*34 + m0 + ml + 8];
            unsigned al0 = lp[ka*34 + m0 + ml];
            unsigned al1 = lp[ka*34 + m0 + ml + 8];
            unsigned al2 = lp[(ka+4)*34 + m0 + ml];
            unsigned al3 = lp[(ka+4)*34 + m0 + ml + 8];
            #pragma unroll
            for (int j = 0; j < 6; ++j) {
                int t = ng + 4*j;     // 0..23
                int n = t*8 + ml;
                unsigned bh0 = d_woH[(size_t)ka*192 + n];
                unsigned bh1 = d_woH[(size_t)(ka+4)*192 + n];
                unsigned bl0 = d_woL[(size_t)ka*192 + n];
                unsigned bl1 = d_woL[(size_t)(ka+4)*192 + n];
                mma_tf32(acc[j][0], acc[j][1], acc[j][2], acc[j][3],
                         ah0, ah1, ah2, ah3, bh0, bh1);
                mma_tf32(acc[j][0], acc[j][1], acc[j][2], acc[j][3],
                         al0, al1, al2, al3, bh0, bh1);
                mma_tf32(acc[j][0], acc[j][1], acc[j][2], acc[j][3],
                         ah0, ah1, ah2, ah3, bl0, bl1);
            }
        }
        // epilogue: bias + write out (float2 stores, cols even-aligned)
        #pragma unroll
        for (int j = 0; j < 6; ++j) {
            int t = ng + 4*j;
            int c0 = t*8 + (lane & 3)*2;
            float bb0 = w_o_b[c0]     + e_def[c0];
            float bb1 = w_o_b[c0 + 1] + e_def[c0 + 1];
            int r0 = m0 + (lane >> 2);
            float2 v0 = make_float2(acc[j][0] + bb0, acc[j][1] + bb1);
            float2 v1 = make_float2(acc[j][2] + bb0, acc[j][3] + bb1);
            *(float2*)(out + ((size_t)bk*RR + r0    )*192 + c0) = v0;
            *(float2*)(out + ((size_t)bk*RR + r0 + 8)*192 + c0) = v1;
        }
    }
}

// ---------------- launch ------------------------------------------------------
extern "C" void kernel_launch(void* const* d_in, const int* in_sizes, int n_in,
                              void* d_out, int out_size)
{
    const float* h     = (const float*)d_in[0];
    const int*   top   = (const int*)  d_in[1];
    const float* qc    = (const float*)d_in[2];
    const float* g     = (const float*)d_in[3];
    const float* L2p   = (const float*)d_in[4];
    const float* L3p   = (const float*)d_in[5];
    const float* L4p   = (const float*)d_in[6];
    const float* w_u_w = (const float*)d_in[7];
    const float* w_u_b = (const float*)d_in[8];
    const float* ln_g  = (const float*)d_in[9];
    const float* ln_b  = (const float*)d_in[10];
    const float* w_d_w = (const float*)d_in[11];
    const float* w_d_b = (const float*)d_in[12];
    const float* w_a_w = (const float*)d_in[13];
    const float* w_a_b = (const float*)d_in[14];
    const float* w_o_w = (const float*)d_in[15];
    const float* w_o_b = (const float*)d_in[16];
    const float* e_def = (const float*)d_in[17];
    float* out = (float*)d_out;

    // launch 0: merged weight prep (tf32 layouts) + row-vectorized transpose
    prep_all_kernel<<<2752, 256>>>(w_u_w, w_d_w, w_a_w, w_o_w, L2p, L3p, L4p);
    // launch 1: precompute (g then h)
    pre_fast_kernel<<<320, 192>>>(g, h, w_u_b);
    // launch 2: main fused kernel
    const int smem_bytes = SM_TOTF * 4;
    cudaFuncSetAttribute(main_kernel, cudaFuncAttributeMaxDynamicSharedMemorySize, smem_bytes);
    main_kernel<<<BB*KK, 256, smem_bytes>>>(top, qc, ln_g, ln_b,
                                            w_d_b, w_a_b, w_o_b, e_def, out);
}